// round 2
// baseline (speedup 1.0000x reference)
#include <cuda_runtime.h>
#include <stdint.h>

#define N_NODES 50000
#define N_EDGES 800000
#define D 96
#define DC 24            // D / 4 (float4 chunks per row)
#define GEMM_ROWS 32     // rows per block in GEMM
#define GEMM_THREADS 192 // 24 out-chunks x 8 row-groups

// Scratch (device globals; no allocation allowed)
__device__ int   g_is64;
__device__ float g_deg[N_NODES];
__device__ float g_dinv[N_NODES];
__device__ float g_h[(size_t)N_NODES * D];

// ---------------------------------------------------------------------------
// 0. Detect edge_index dtype (int32 vs int64). For int64 little-endian values
//    < 2^31, odd int32 words are all zero; random int32 node ids are not.
// ---------------------------------------------------------------------------
__global__ void detect_idx_kernel(const int* __restrict__ ei32) {
    // single thread, trivial cost
    int looks64 = 1;
    int any_nonzero = 0;
    for (int i = 0; i < 64; i++) {
        int lo = ei32[2 * i];
        int hi = ei32[2 * i + 1];
        if (hi != 0) looks64 = 0;
        if (lo != 0) any_nonzero = 1;
    }
    g_is64 = (looks64 && any_nonzero) ? 1 : 0;
}

__device__ __forceinline__ int load_idx(const void* ei, size_t k) {
    return g_is64 ? (int)((const long long*)ei)[k] : ((const int*)ei)[k];
}

// ---------------------------------------------------------------------------
// 1. deg init: self-loop contributes weight 1 to every node
// ---------------------------------------------------------------------------
__global__ void init_deg_kernel() {
    int i = blockIdx.x * blockDim.x + threadIdx.x;
    if (i < N_NODES) g_deg[i] = 1.0f;
}

// ---------------------------------------------------------------------------
// 2. deg accumulation over edges: deg[col] += ew
// ---------------------------------------------------------------------------
__global__ void accum_deg_kernel(const void* __restrict__ ei,
                                 const float* __restrict__ ew) {
    int e = blockIdx.x * blockDim.x + threadIdx.x;
    if (e < N_EDGES) {
        int col = load_idx(ei, (size_t)N_EDGES + e);
        atomicAdd(&g_deg[col], ew[e]);
    }
}

// ---------------------------------------------------------------------------
// 3. dinv = rsqrt(deg)
// ---------------------------------------------------------------------------
__global__ void dinv_kernel() {
    int i = blockIdx.x * blockDim.x + threadIdx.x;
    if (i < N_NODES) {
        float d = g_deg[i];
        g_dinv[i] = (d > 0.0f) ? rsqrtf(d) : 0.0f;
    }
}

// ---------------------------------------------------------------------------
// 4. GEMM: h = x @ W   (x: [N,96], W: [96,96])
//    192 threads = 24 out-chunks (tx) x 8 row-groups (ty); 4x4 register tile.
// ---------------------------------------------------------------------------
__global__ __launch_bounds__(GEMM_THREADS)
void gemm_kernel(const float* __restrict__ x, const float* __restrict__ W) {
    __shared__ float Ws[D * D];          // 36864 B
    __shared__ float Xs[GEMM_ROWS * D];  // 12288 B

    int tid = threadIdx.x;
    int row0 = blockIdx.x * GEMM_ROWS;

    const float4* W4 = (const float4*)W;
    float4* Ws4 = (float4*)Ws;
    #pragma unroll
    for (int i = tid; i < D * DC; i += GEMM_THREADS) Ws4[i] = W4[i];

    const float4* X4 = (const float4*)x;
    float4* Xs4 = (float4*)Xs;
    #pragma unroll
    for (int i = tid; i < GEMM_ROWS * DC; i += GEMM_THREADS) {
        int r = i / DC;
        int c = i - r * DC;
        int gr = row0 + r;
        Xs4[i] = (gr < N_NODES) ? X4[(size_t)gr * DC + c]
                                : make_float4(0.f, 0.f, 0.f, 0.f);
    }
    __syncthreads();

    int tx = tid % DC;       // output float4 chunk
    int ty = tid / DC;       // row group 0..7
    int rbase = ty * 4;

    float4 acc0 = make_float4(0.f, 0.f, 0.f, 0.f);
    float4 acc1 = acc0, acc2 = acc0, acc3 = acc0;

    #pragma unroll 4
    for (int kc = 0; kc < DC; kc++) {
        float4 xv0 = Xs4[(rbase + 0) * DC + kc];
        float4 xv1 = Xs4[(rbase + 1) * DC + kc];
        float4 xv2 = Xs4[(rbase + 2) * DC + kc];
        float4 xv3 = Xs4[(rbase + 3) * DC + kc];
        const float* p0 = (const float*)&xv0;
        const float* p1 = (const float*)&xv1;
        const float* p2 = (const float*)&xv2;
        const float* p3 = (const float*)&xv3;
        #pragma unroll
        for (int kk = 0; kk < 4; kk++) {
            float4 wv = Ws4[(kc * 4 + kk) * DC + tx];
            float a0 = p0[kk], a1 = p1[kk], a2 = p2[kk], a3 = p3[kk];
            acc0.x += a0 * wv.x; acc0.y += a0 * wv.y; acc0.z += a0 * wv.z; acc0.w += a0 * wv.w;
            acc1.x += a1 * wv.x; acc1.y += a1 * wv.y; acc1.z += a1 * wv.z; acc1.w += a1 * wv.w;
            acc2.x += a2 * wv.x; acc2.y += a2 * wv.y; acc2.z += a2 * wv.z; acc2.w += a2 * wv.w;
            acc3.x += a3 * wv.x; acc3.y += a3 * wv.y; acc3.z += a3 * wv.z; acc3.w += a3 * wv.w;
        }
    }

    float4* H4 = (float4*)g_h;
    int gr = row0 + rbase;
    if (gr + 0 < N_NODES) H4[(size_t)(gr + 0) * DC + tx] = acc0;
    if (gr + 1 < N_NODES) H4[(size_t)(gr + 1) * DC + tx] = acc1;
    if (gr + 2 < N_NODES) H4[(size_t)(gr + 2) * DC + tx] = acc2;
    if (gr + 3 < N_NODES) H4[(size_t)(gr + 3) * DC + tx] = acc3;
}

// ---------------------------------------------------------------------------
// 5. out init: out[n] = b + h[n] * dinv[n]^2   (self-loop contribution + bias)
// ---------------------------------------------------------------------------
__global__ void init_out_kernel(const float* __restrict__ b,
                                float* __restrict__ out) {
    int i = blockIdx.x * blockDim.x + threadIdx.x;  // over N_NODES * DC
    if (i < N_NODES * DC) {
        int n = i / DC;
        int c = i - n * DC;
        float s = g_dinv[n];
        s = s * s;
        float4 hv = ((const float4*)g_h)[i];
        float4 bv = ((const float4*)b)[c];
        float4 o;
        o.x = bv.x + hv.x * s;
        o.y = bv.y + hv.y * s;
        o.z = bv.z + hv.z * s;
        o.w = bv.w + hv.w * s;
        ((float4*)out)[i] = o;
    }
}

// ---------------------------------------------------------------------------
// 6. Scatter: one warp per edge. out[col] += h[row] * (dinv[row]*ew*dinv[col])
//    Vectorized global reduction (red.global.add.v4.f32, sm_90+).
// ---------------------------------------------------------------------------
__global__ __launch_bounds__(256)
void scatter_kernel(const void* __restrict__ ei,
                    const float* __restrict__ ew,
                    float* __restrict__ out) {
    int warp = (blockIdx.x * blockDim.x + threadIdx.x) >> 5;
    int lane = threadIdx.x & 31;
    if (warp >= N_EDGES) return;
    if (lane < DC) {
        int e = warp;
        int row = load_idx(ei, e);                    // broadcast loads
        int col = load_idx(ei, (size_t)N_EDGES + e);
        float norm = g_dinv[row] * ew[e] * g_dinv[col];
        float4 hv = ((const float4*)g_h)[(size_t)row * DC + lane];
        float mx = hv.x * norm, my = hv.y * norm, mz = hv.z * norm, mw = hv.w * norm;
        float* addr = out + (size_t)col * D + lane * 4;
        asm volatile("red.global.add.v4.f32 [%0], {%1, %2, %3, %4};"
                     :: "l"(addr), "f"(mx), "f"(my), "f"(mz), "f"(mw)
                     : "memory");
    }
}

// ---------------------------------------------------------------------------
// Launch
// Inputs (metadata order): x[N*96] f32, edge_index[2*E] int (32 or 64),
//                          edge_weight[E] f32, W[96*96] f32, b[96] f32.
// Output: [N*96] f32.
// ---------------------------------------------------------------------------
extern "C" void kernel_launch(void* const* d_in, const int* in_sizes, int n_in,
                              void* d_out, int out_size) {
    const float* x = (const float*)d_in[0];
    const void* ei = d_in[1];
    const float* ew = (const float*)d_in[2];
    const float* W = (const float*)d_in[3];
    const float* b = (const float*)d_in[4];
    float* out = (float*)d_out;

    detect_idx_kernel<<<1, 1>>>((const int*)ei);
    init_deg_kernel<<<(N_NODES + 255) / 256, 256>>>();
    accum_deg_kernel<<<(N_EDGES + 255) / 256, 256>>>(ei, ew);
    dinv_kernel<<<(N_NODES + 255) / 256, 256>>>();
    gemm_kernel<<<(N_NODES + GEMM_ROWS - 1) / GEMM_ROWS, GEMM_THREADS>>>(x, W);
    init_out_kernel<<<(N_NODES * DC + 255) / 256, 256>>>(b, out);
    scatter_kernel<<<(N_EDGES + 7) / 8, 256>>>(ei, ew, out);
}

// round 5
// speedup vs baseline: 1.6278x; 1.6278x over previous
#include <cuda_runtime.h>
#include <stdint.h>

#define N_NODES 50000
#define N_EDGES 800000
#define D 96
#define DC 24            // D / 4 (float4 chunks per row)
#define GEMM_ROWS 32
#define GEMM_THREADS 192

// Scratch (device globals; no allocation allowed)
__device__ int   g_is64;
__device__ float g_deg[N_NODES];
__device__ float g_dinv[N_NODES];
__device__ float g_h[(size_t)N_NODES * D];     // stores h * dinv[row]
__device__ int4  g_edge[N_EDGES];              // {row, col, bits(ew*dinv[col]), pad}

__device__ __forceinline__ int load_idx(const void* ei, size_t k) {
    return g_is64 ? (int)((const long long*)ei)[k] : ((const int*)ei)[k];
}

// ---------------------------------------------------------------------------
// 1. init: deg = 1 (self loop); thread 0 detects edge_index dtype.
//    int64 values < 2^31 have all-zero odd words; random int32 ids do not.
// ---------------------------------------------------------------------------
__global__ void init_kernel(const int* __restrict__ ei32) {
    int i = blockIdx.x * blockDim.x + threadIdx.x;
    if (i < N_NODES) g_deg[i] = 1.0f;
    if (i == 0) {
        int looks64 = 1, any_nonzero = 0;
        for (int k = 0; k < 64; k++) {
            if (ei32[2 * k + 1] != 0) looks64 = 0;
            if (ei32[2 * k] != 0) any_nonzero = 1;
        }
        g_is64 = (looks64 && any_nonzero) ? 1 : 0;
    }
}

// ---------------------------------------------------------------------------
// 2. deg[col] += ew
// ---------------------------------------------------------------------------
__global__ void accum_deg_kernel(const void* __restrict__ ei,
                                 const float* __restrict__ ew) {
    int e = blockIdx.x * blockDim.x + threadIdx.x;
    if (e < N_EDGES) {
        int col = load_idx(ei, (size_t)N_EDGES + e);
        atomicAdd(&g_deg[col], ew[e]);
    }
}

// ---------------------------------------------------------------------------
// 3. dinv = rsqrt(deg)
// ---------------------------------------------------------------------------
__global__ void dinv_kernel() {
    int i = blockIdx.x * blockDim.x + threadIdx.x;
    if (i < N_NODES) {
        float d = g_deg[i];
        g_dinv[i] = (d > 0.0f) ? rsqrtf(d) : 0.0f;
    }
}

// ---------------------------------------------------------------------------
// 4. per-edge metadata: {row, col, ew * dinv[col]}
//    (dinv[row] factor is pre-folded into g_h by the GEMM epilogue)
// ---------------------------------------------------------------------------
__global__ void norm_kernel(const void* __restrict__ ei,
                            const float* __restrict__ ew) {
    int e = blockIdx.x * blockDim.x + threadIdx.x;
    if (e < N_EDGES) {
        int row = load_idx(ei, e);
        int col = load_idx(ei, (size_t)N_EDGES + e);
        float nrm = ew[e] * g_dinv[col];
        g_edge[e] = make_int4(row, col, __float_as_int(nrm), 0);
    }
}

// ---------------------------------------------------------------------------
// 5. GEMM + epilogue:  h' = (x @ W) * dinv[row]  -> g_h
//                      out[row] = b + h' * dinv[row]   (self loop + bias)
// ---------------------------------------------------------------------------
__global__ __launch_bounds__(GEMM_THREADS)
void gemm_kernel(const float* __restrict__ x, const float* __restrict__ W,
                 const float* __restrict__ b, float* __restrict__ out) {
    __shared__ float Ws[D * D];
    __shared__ float Xs[GEMM_ROWS * D];

    int tid = threadIdx.x;
    int row0 = blockIdx.x * GEMM_ROWS;

    const float4* W4 = (const float4*)W;
    float4* Ws4 = (float4*)Ws;
    #pragma unroll
    for (int i = tid; i < D * DC; i += GEMM_THREADS) Ws4[i] = W4[i];

    const float4* X4 = (const float4*)x;
    float4* Xs4 = (float4*)Xs;
    #pragma unroll
    for (int i = tid; i < GEMM_ROWS * DC; i += GEMM_THREADS) {
        int r = i / DC;
        int c = i - r * DC;
        int gr = row0 + r;
        Xs4[i] = (gr < N_NODES) ? X4[(size_t)gr * DC + c]
                                : make_float4(0.f, 0.f, 0.f, 0.f);
    }
    __syncthreads();

    int tx = tid % DC;       // output float4 chunk
    int ty = tid / DC;       // row group 0..7
    int rbase = ty * 4;

    float4 acc[4];
    #pragma unroll
    for (int r = 0; r < 4; r++) acc[r] = make_float4(0.f, 0.f, 0.f, 0.f);

    #pragma unroll 4
    for (int kc = 0; kc < DC; kc++) {
        float4 xv[4];
        #pragma unroll
        for (int r = 0; r < 4; r++) xv[r] = Xs4[(rbase + r) * DC + kc];
        #pragma unroll
        for (int kk = 0; kk < 4; kk++) {
            float4 wv = Ws4[(kc * 4 + kk) * DC + tx];
            #pragma unroll
            for (int r = 0; r < 4; r++) {
                float a = ((const float*)&xv[r])[kk];
                acc[r].x += a * wv.x; acc[r].y += a * wv.y;
                acc[r].z += a * wv.z; acc[r].w += a * wv.w;
            }
        }
    }

    float4 bv = ((const float4*)b)[tx];
    float4* H4 = (float4*)g_h;
    float4* O4 = (float4*)out;
    #pragma unroll
    for (int r = 0; r < 4; r++) {
        int gr = row0 + rbase + r;
        if (gr < N_NODES) {
            float s = g_dinv[gr];
            float4 hv;  // h * dinv
            hv.x = acc[r].x * s; hv.y = acc[r].y * s;
            hv.z = acc[r].z * s; hv.w = acc[r].w * s;
            H4[(size_t)gr * DC + tx] = hv;
            float4 o;   // b + h * dinv^2
            o.x = bv.x + hv.x * s; o.y = bv.y + hv.y * s;
            o.z = bv.z + hv.z * s; o.w = bv.w + hv.w * s;
            O4[(size_t)gr * DC + tx] = o;
        }
    }
}

// ---------------------------------------------------------------------------
// 6. Scatter: thread t -> edge t/24, chunk t%24 (all 32 lanes active).
//    out[col] += h'[row] * (ew * dinv[col])   via red.global.add.v4.f32
// ---------------------------------------------------------------------------
__global__ __launch_bounds__(256)
void scatter_kernel(float* __restrict__ out) {
    int idx = blockIdx.x * blockDim.x + threadIdx.x;
    if (idx >= N_EDGES * DC) return;
    int e = idx / DC;
    int c = idx - e * DC;
    int4 m = g_edge[e];               // warp-coalesced broadcast
    int row = m.x, col = m.y;
    float norm = __int_as_float(m.z);
    float4 hv = ((const float4*)g_h)[(size_t)row * DC + c];
    float mx = hv.x * norm, my = hv.y * norm, mz = hv.z * norm, mw = hv.w * norm;
    float* addr = out + (size_t)col * D + c * 4;
    asm volatile("red.global.add.v4.f32 [%0], {%1, %2, %3, %4};"
                 :: "l"(addr), "f"(mx), "f"(my), "f"(mz), "f"(mw)
                 : "memory");
}

// ---------------------------------------------------------------------------
// Launch.  Inputs: x[N*96] f32, edge_index[2*E] int32/int64, edge_weight[E] f32,
//                  W[96*96] f32, b[96] f32.  Output: [N*96] f32.
// ---------------------------------------------------------------------------
extern "C" void kernel_launch(void* const* d_in, const int* in_sizes, int n_in,
                              void* d_out, int out_size) {
    const float* x = (const float*)d_in[0];
    const void* ei = d_in[1];
    const float* ew = (const float*)d_in[2];
    const float* W = (const float*)d_in[3];
    const float* b = (const float*)d_in[4];
    float* out = (float*)d_out;

    init_kernel<<<(N_NODES + 255) / 256, 256>>>((const int*)ei);
    accum_deg_kernel<<<(N_EDGES + 255) / 256, 256>>>(ei, ew);
    dinv_kernel<<<(N_NODES + 255) / 256, 256>>>();
    norm_kernel<<<(N_EDGES + 255) / 256, 256>>>(ei, ew);
    gemm_kernel<<<(N_NODES + GEMM_ROWS - 1) / GEMM_ROWS, GEMM_THREADS>>>(x, W, b, out);
    scatter_kernel<<<(N_EDGES * DC + 255) / 256, 256>>>(out);
}